// round 13
// baseline (speedup 1.0000x reference)
#include <cuda_runtime.h>
#include <cstdint>

// ---------------- problem constants ----------------
#define T_LEN   16384
#define CH      128
#define BATCH   8
#define NLAYER  63
#define N0SKIP  27
#define TM_L    128

#define ACT_ELEMS (8u * 16384u * 128u)   // 16,777,216

// layer smem: Au [2 ks2][128 m][4 tig] uint4 = 1024 u4 (16KB)
//             Yp [8 ks2][128 m][4 tig] uint4 = 4096 u4 (64KB)
#define AU_U4 1024
#define YP_U4 4096
#define SMEM_LAYER_BYTES ((AU_U4 + YP_U4) * 16)   // 81920

// split activation buffers: uint4 per (b, t, ks 0..7, tig 0..3)
#define SP_ELEMS (8u * 16384u * 32u)     // 4,194,304 uint4 = 64MB each

// post kernel (FFMA2)
#define KC          32
#define TM_P        64
#define AS2_STRIDE  68
#define S1_STRIDE   68
#define S2_STRIDE   133
#define SMEM_POST_FLOATS (KC*AS2_STRIDE + KC*CH + CH*S1_STRIDE + TM_P*S2_STRIDE)
#define SMEM_POST_BYTES  (SMEM_POST_FLOATS * 4)    // 93952

// ---------------- device scratch ----------------
__device__ float g_bufA[ACT_ELEMS];
__device__ float g_bufB[ACT_ELEMS];
__device__ float g_skip[ACT_ELEMS];
__device__ uint4 g_spA[SP_ELEMS];   // split(relu(x)) fragment-packed, ping
__device__ uint4 g_spB[SP_ELEMS];   // pong
// bf16 hi/lo fragment-packed weights: uint4 = {hi_pair_k, hi_pair_k8, lo_pair_k, lo_pair_k8}
__device__ uint4 g_w3f[NLAYER * 3 * 8 * 128 * 4];   // [cnt][tap][ks16][n][tig]
__device__ uint4 g_wdf[NLAYER * 8 * 128 * 4];       // [cnt][ks16][n][tig]
__device__ uint4 g_wsf[NLAYER * 8 * 128 * 4];       // [cnt][ks16][n][tig]
__device__ float g_p1t[CH * CH];                    // [c][n]
__device__ float g_p2t[CH * 256];                   // [n][q]

// ---------------- helpers ----------------
__device__ __forceinline__ unsigned pack_bf16x2(float lo_val, float hi_val) {
    unsigned r;
    asm("cvt.rn.bf16x2.f32 %0, %1, %2;" : "=r"(r) : "f"(hi_val), "f"(lo_val));
    return r;
}
__device__ __forceinline__ void split_pair(float v0, float v1, unsigned& h, unsigned& l) {
    h = pack_bf16x2(v0, v1);
    float h0 = __uint_as_float(h << 16);
    float h1 = __uint_as_float(h & 0xFFFF0000u);
    l = pack_bf16x2(v0 - h0, v1 - h1);
}
__device__ __forceinline__ void mma16(float* d,
                                      unsigned a0, unsigned a1, unsigned a2, unsigned a3,
                                      unsigned b0, unsigned b1) {
    asm("mma.sync.aligned.m16n8k16.row.col.f32.bf16.bf16.f32 "
        "{%0,%1,%2,%3}, {%4,%5,%6,%7}, {%8,%9}, {%0,%1,%2,%3};"
        : "+f"(d[0]), "+f"(d[1]), "+f"(d[2]), "+f"(d[3])
        : "r"(a0), "r"(a1), "r"(a2), "r"(a3), "r"(b0), "r"(b1));
}
__device__ __forceinline__ unsigned long long fma2(unsigned long long a,
                                                   unsigned long long b,
                                                   unsigned long long c) {
    unsigned long long d;
    asm("fma.rn.f32x2 %0, %1, %2, %3;" : "=l"(d) : "l"(a), "l"(b), "l"(c));
    return d;
}
__device__ __forceinline__ unsigned long long dup2(float x) {
    unsigned long long d;
    asm("mov.b64 %0, {%1, %1};" : "=l"(d) : "f"(x));
    return d;
}
__device__ __forceinline__ unsigned long long pack2(float lo, float hi) {
    unsigned long long d;
    asm("mov.b64 %0, {%1, %2};" : "=l"(d) : "f"(lo), "f"(hi));
    return d;
}
__device__ __forceinline__ void unpack2(unsigned long long v, float& lo, float& hi) {
    asm("mov.b64 {%0, %1}, %2;" : "=f"(lo), "=f"(hi) : "l"(v));
}

// ---------------- weight prep: split + fragment-pack ----------------
__global__ void prep_kernel(const float* __restrict__ dcnn_w,
                            const float* __restrict__ dense_w,
                            const float* __restrict__ skip_w,
                            const float* __restrict__ p1w,
                            const float* __restrict__ p2w) {
    int gs  = gridDim.x * blockDim.x;
    int tid = blockIdx.x * blockDim.x + threadIdx.x;

    const int N3 = NLAYER * 3 * 8 * 128 * 4;
    for (int idx = tid; idx < N3; idx += gs) {
        int tig = idx & 3;
        int n   = (idx >> 2) & 127;
        int ks  = (idx >> 9) & 7;
        int rest = idx >> 12;
        int tap = rest % 3;
        int cnt = rest / 3;
        int k0 = ks * 16 + 2 * tig;
        const float* src = dcnn_w + ((size_t)(cnt * CH + n) * CH) * 3 + tap;
        float w0 = src[(k0 + 0) * 3];
        float w1 = src[(k0 + 1) * 3];
        float w8 = src[(k0 + 8) * 3];
        float w9 = src[(k0 + 9) * 3];
        unsigned hx, lx, hy, ly;
        split_pair(w0, w1, hx, lx);
        split_pair(w8, w9, hy, ly);
        g_w3f[idx] = make_uint4(hx, hy, lx, ly);
    }
    const int N1 = NLAYER * 8 * 128 * 4;
    for (int idx = tid; idx < N1; idx += gs) {
        int tig = idx & 3;
        int n   = (idx >> 2) & 127;
        int ks  = (idx >> 9) & 7;
        int cnt = idx >> 12;
        int k0 = ks * 16 + 2 * tig;
        {
            const float* src = dense_w + (size_t)(cnt * CH + n) * CH;
            unsigned hx, lx, hy, ly;
            split_pair(src[k0], src[k0 + 1], hx, lx);
            split_pair(src[k0 + 8], src[k0 + 9], hy, ly);
            g_wdf[idx] = make_uint4(hx, hy, lx, ly);
        }
        {
            const float* src = skip_w + (size_t)(cnt * CH + n) * CH;
            unsigned hx, lx, hy, ly;
            split_pair(src[k0], src[k0 + 1], hx, lx);
            split_pair(src[k0 + 8], src[k0 + 9], hy, ly);
            g_wsf[idx] = make_uint4(hx, hy, lx, ly);
        }
    }
    for (int idx = tid; idx < CH * CH; idx += gs) {
        int n = idx & 127;
        int c = idx >> 7;
        g_p1t[idx] = p1w[n * CH + c];
    }
    for (int idx = tid; idx < CH * 256; idx += gs) {
        int q = idx & 255;
        int n = idx >> 8;
        g_p2t[idx] = p2w[q * CH + n];
    }
}

// ---------------- causal conv (k=25, pad 12), 1 -> 128 channels ----------------
__global__ void causal_kernel(const float* __restrict__ x,
                              const float* __restrict__ cw,
                              const float* __restrict__ cb) {
    __shared__ float xs[64 + 24];
    int b  = blockIdx.y;
    int t0 = blockIdx.x * 64;
    int c  = threadIdx.x;

    for (int i = threadIdx.x; i < 88; i += 128) {
        int t = t0 - 12 + i;
        xs[i] = ((unsigned)t < T_LEN) ? x[(size_t)b * T_LEN + t] : 0.f;
    }
    __syncthreads();

    float w[25];
#pragma unroll
    for (int k = 0; k < 25; ++k) w[k] = cw[c * 25 + k];
    float bias = cb[c];

    float* out = g_bufA + (size_t)b * T_LEN * CH;
    for (int tt = 0; tt < 64; ++tt) {
        float s = bias;
#pragma unroll
        for (int k = 0; k < 25; ++k) s += w[k] * xs[tt + k];
        out[(size_t)(t0 + tt) * CH + c] = s;
    }
}

// ---------------- initial split of relu(g_bufA) into g_spA ----------------
__global__ void split0_kernel() {
    unsigned idx = blockIdx.x * blockDim.x + threadIdx.x;   // one uint4 each
    if (idx >= SP_ELEMS) return;
    int tig = idx & 3;
    int ks  = (idx >> 2) & 7;
    unsigned bt = idx >> 5;
    const float* row = g_bufA + (size_t)bt * CH;
    int c0 = ks * 16 + 2 * tig;
    unsigned h0, l0, h1, l1;
    split_pair(fmaxf(row[c0], 0.f),     fmaxf(row[c0 + 1], 0.f), h0, l0);
    split_pair(fmaxf(row[c0 + 8], 0.f), fmaxf(row[c0 + 9], 0.f), h1, l1);
    g_spA[idx] = make_uint4(h0, h1, l0, l1);
}

// ---------------- one residual layer (bf16x3 mma.sync, 8 warps) ----------------
// y = relu(dconv(relu(xin)) + b3) ; skip (+)= y@Ws + bs ; xout = y@Wd + bd + xin
// A operands come pre-split from g_spX (fragment-packed); dense epilogue writes
// the next layer's split buffer.
__global__ void __launch_bounds__(256, 2)
layer_kernel(int cnt, int dil, int skip_mode, int do_dense, int pp,
             const float* __restrict__ dcnn_b,
             const float* __restrict__ dense_b,
             const float* __restrict__ skip_b) {
    extern __shared__ uint4 smu[];
    uint4* Au = smu;            // [2][128][4]
    uint4* Yp = smu + AU_U4;    // [8][128][4]

    const float* xin  = pp ? g_bufB : g_bufA;
    float*       xout = pp ? g_bufA : g_bufB;
    const uint4* spIn = pp ? g_spB : g_spA;
    uint4*       spOut = pp ? g_spA : g_spB;

    int b   = blockIdx.y;
    int t0  = blockIdx.x * TM_L;
    int tid = threadIdx.x;
    int lane = tid & 31, w = tid >> 5;
    int gid = lane >> 2, tig = lane & 3;
    int mw = w & 3, nw = w >> 2;       // 4 m-warps x 2 n-warps
    int m0 = mw * 32, n0 = nw * 64;

    const float* xinB = xin + (size_t)b * T_LEN * CH;
    const uint4* spInB = spIn + (size_t)b * T_LEN * 32;

    float acc[2][8][4];
#pragma unroll
    for (int mt = 0; mt < 2; ++mt)
#pragma unroll
        for (int nt = 0; nt < 8; ++nt)
#pragma unroll
            for (int q = 0; q < 4; ++q) acc[mt][nt][q] = 0.f;

    // ---- stage 1: y = relu(dilated 3-tap conv of relu(xin)) ----
#pragma unroll 1
    for (int tap = 0; tap < 3; ++tap) {
        int shift = (tap - 1) * dil;
        const uint4* wtap = g_w3f + (size_t)((cnt * 3 + tap) * 8) * 512;
#pragma unroll 1
        for (int kbi = 0; kbi < 4; ++kbi) {
            __syncthreads();
            // stage A: straight copy of pre-split fragments into Au
#pragma unroll
            for (int it = 0; it < 4; ++it) {
                int e    = tid + it * 256;   // 1024 uint4: 128 m x 2 ks2 x 4 tig
                int m    = e >> 3;
                int r    = e & 7;
                int ks2  = r >> 2;
                int tigc = r & 3;
                int t    = t0 + m + shift;
                uint4 v = make_uint4(0u, 0u, 0u, 0u);
                if ((unsigned)t < T_LEN)
                    v = spInB[(size_t)t * 32 + (kbi * 2 + ks2) * 4 + tigc];
                Au[(ks2 * 128 + m) * 4 + tigc] = v;
            }
            __syncthreads();
#pragma unroll
            for (int ks2 = 0; ks2 < 2; ++ks2) {
                const uint4* bbase = wtap + (size_t)(kbi * 2 + ks2) * 512;
                uint4 bf[8];
#pragma unroll
                for (int nt = 0; nt < 8; ++nt)
                    bf[nt] = bbase[(n0 + nt * 8 + gid) * 4 + tig];
#pragma unroll
                for (int mt = 0; mt < 2; ++mt) {
                    int r = m0 + mt * 16 + gid;
                    uint4 alo = Au[(ks2 * 128 + r) * 4 + tig];
                    uint4 ahi = Au[(ks2 * 128 + r + 8) * 4 + tig];
#pragma unroll
                    for (int nt = 0; nt < 8; ++nt) {
                        mma16(acc[mt][nt], alo.x, ahi.x, alo.y, ahi.y, bf[nt].x, bf[nt].y);
                        mma16(acc[mt][nt], alo.x, ahi.x, alo.y, ahi.y, bf[nt].z, bf[nt].w);
                        mma16(acc[mt][nt], alo.z, ahi.z, alo.w, ahi.w, bf[nt].x, bf[nt].y);
                    }
                }
            }
        }
    }

    // stage-1 epilogue: bias + relu -> Yp (fragment-packed hi/lo)
    {
        const float* db = dcnn_b + cnt * CH;
        __syncthreads();
#pragma unroll
        for (int p = 0; p < 4; ++p) {
            int chE = n0 + (2 * p) * 8 + 2 * tig;
            int chO = chE + 8;
            float2 bE = *(const float2*)(db + chE);
            float2 bO = *(const float2*)(db + chO);
#pragma unroll
            for (int mt = 0; mt < 2; ++mt) {
                int r = m0 + mt * 16 + gid;
                unsigned hE, lE, hO, lO;
                split_pair(fmaxf(acc[mt][2 * p][0] + bE.x, 0.f),
                           fmaxf(acc[mt][2 * p][1] + bE.y, 0.f), hE, lE);
                split_pair(fmaxf(acc[mt][2 * p + 1][0] + bO.x, 0.f),
                           fmaxf(acc[mt][2 * p + 1][1] + bO.y, 0.f), hO, lO);
                Yp[((nw * 4 + p) * 128 + r) * 4 + tig] = make_uint4(hE, hO, lE, lO);
                split_pair(fmaxf(acc[mt][2 * p][2] + bE.x, 0.f),
                           fmaxf(acc[mt][2 * p][3] + bE.y, 0.f), hE, lE);
                split_pair(fmaxf(acc[mt][2 * p + 1][2] + bO.x, 0.f),
                           fmaxf(acc[mt][2 * p + 1][3] + bO.y, 0.f), hO, lO);
                Yp[((nw * 4 + p) * 128 + r + 8) * 4 + tig] = make_uint4(hE, hO, lE, lO);
            }
        }
    }
    __syncthreads();

    // ---- stage 2: skip GEMM (g=0) and dense GEMM (g=1), A = Yp ----
#pragma unroll 1
    for (int g = 0; g < 2; ++g) {
        if (g == 0 && skip_mode == 0) continue;
        if (g == 1 && !do_dense) continue;
        const uint4* wbase = (g == 0 ? g_wsf : g_wdf) + (size_t)(cnt * 8) * 512;
#pragma unroll
        for (int mt = 0; mt < 2; ++mt)
#pragma unroll
            for (int nt = 0; nt < 8; ++nt)
#pragma unroll
                for (int q = 0; q < 4; ++q) acc[mt][nt][q] = 0.f;

#pragma unroll 1
        for (int ky = 0; ky < 8; ++ky) {
            const uint4* bbase = wbase + (size_t)ky * 512;
            uint4 bf[8];
#pragma unroll
            for (int nt = 0; nt < 8; ++nt)
                bf[nt] = bbase[(n0 + nt * 8 + gid) * 4 + tig];
#pragma unroll
            for (int mt = 0; mt < 2; ++mt) {
                int r = m0 + mt * 16 + gid;
                uint4 alo = Yp[(ky * 128 + r) * 4 + tig];
                uint4 ahi = Yp[(ky * 128 + r + 8) * 4 + tig];
#pragma unroll
                for (int nt = 0; nt < 8; ++nt) {
                    mma16(acc[mt][nt], alo.x, ahi.x, alo.y, ahi.y, bf[nt].x, bf[nt].y);
                    mma16(acc[mt][nt], alo.x, ahi.x, alo.y, ahi.y, bf[nt].z, bf[nt].w);
                    mma16(acc[mt][nt], alo.z, ahi.z, alo.w, ahi.w, bf[nt].x, bf[nt].y);
                }
            }
        }

        if (g == 0) {
            const float* sb = skip_b + cnt * CH;
            float* skB = g_skip + (size_t)b * T_LEN * CH;
#pragma unroll
            for (int nt = 0; nt < 8; ++nt) {
                int ch = n0 + nt * 8 + 2 * tig;
                float2 bb = *(const float2*)(sb + ch);
#pragma unroll
                for (int mt = 0; mt < 2; ++mt) {
                    int t_r = t0 + m0 + mt * 16 + gid;
                    float2* p0 = (float2*)(skB + (size_t)t_r * CH + ch);
                    float2* p1 = (float2*)(skB + (size_t)(t_r + 8) * CH + ch);
                    float2 v0 = make_float2(acc[mt][nt][0] + bb.x, acc[mt][nt][1] + bb.y);
                    float2 v1 = make_float2(acc[mt][nt][2] + bb.x, acc[mt][nt][3] + bb.y);
                    if (skip_mode == 2) {
                        float2 o0 = *p0, o1 = *p1;
                        v0.x += o0.x; v0.y += o0.y;
                        v1.x += o1.x; v1.y += o1.y;
                    }
                    *p0 = v0;
                    *p1 = v1;
                }
            }
        } else {
            // dense epilogue: write xout fp32 AND next layer's split fragments
            const float* dbv = dense_b + cnt * CH;
            float* xoB = xout + (size_t)b * T_LEN * CH;
            uint4* spOutB = spOut + (size_t)b * T_LEN * 32;
#pragma unroll
            for (int ntp = 0; ntp < 4; ++ntp) {
                int nt0 = 2 * ntp, nt1 = nt0 + 1;
                int chE = n0 + nt0 * 8 + 2 * tig;   // half0 pair
                int chO = chE + 8;                  // half1 pair
                int ks  = (n0 >> 4) + ntp;          // split-buffer k-chunk
                float2 bbE = *(const float2*)(dbv + chE);
                float2 bbO = *(const float2*)(dbv + chO);
#pragma unroll
                for (int mt = 0; mt < 2; ++mt) {
                    int t_r = t0 + m0 + mt * 16 + gid;
#pragma unroll
                    for (int rr = 0; rr < 2; ++rr) {
                        int t_cur = t_r + rr * 8;
                        int qb = rr * 2;   // acc slots 0,1 or 2,3
                        float2 xiE = *(const float2*)(xinB + (size_t)t_cur * CH + chE);
                        float2 xiO = *(const float2*)(xinB + (size_t)t_cur * CH + chO);
                        float vE0 = acc[mt][nt0][qb]     + bbE.x + xiE.x;
                        float vE1 = acc[mt][nt0][qb + 1] + bbE.y + xiE.y;
                        float vO0 = acc[mt][nt1][qb]     + bbO.x + xiO.x;
                        float vO1 = acc[mt][nt1][qb + 1] + bbO.y + xiO.y;
                        *(float2*)(xoB + (size_t)t_cur * CH + chE) = make_float2(vE0, vE1);
                        *(float2*)(xoB + (size_t)t_cur * CH + chO) = make_float2(vO0, vO1);
                        unsigned hE, lE, hO, lO;
                        split_pair(fmaxf(vE0, 0.f), fmaxf(vE1, 0.f), hE, lE);
                        split_pair(fmaxf(vO0, 0.f), fmaxf(vO1, 0.f), hO, lO);
                        spOutB[(size_t)t_cur * 32 + ks * 4 + tig] =
                            make_uint4(hE, hO, lE, lO);
                    }
                }
            }
        }
    }
}

// ---------------- post head (FFMA2, fp32) ----------------
__global__ void __launch_bounds__(256, 2)
post_kernel(const float* __restrict__ p1b, const float* __restrict__ p2b,
            float* __restrict__ out) {
    extern __shared__ float sm[];
    float* As  = sm;
    float* Bs  = As + KC * AS2_STRIDE;
    float* S1t = Bs + KC * CH;
    float* S2  = S1t + CH * S1_STRIDE;

    int b    = blockIdx.y;
    int t0   = blockIdx.x * TM_P;
    int tid  = threadIdx.x;
    int lane = tid & 31, warp = tid >> 5;
    int c4   = lane * 4;
    int r8   = warp * 8;

    const float* skB = g_skip + (size_t)b * T_LEN * CH;

    unsigned long long acc[4][4];
#pragma unroll
    for (int i = 0; i < 4; ++i)
#pragma unroll
        for (int j = 0; j < 4; ++j) acc[i][j] = 0ULL;

    for (int k0 = 0; k0 < CH; k0 += KC) {
        __syncthreads();
#pragma unroll
        for (int i = 0; i < 2; ++i) {
            int e4 = tid + i * 256;
            int m  = e4 >> 3;
            int kq = (e4 & 7) * 4;
            float4 v = *(const float4*)(skB + (size_t)(t0 + m) * CH + k0 + kq);
            As[(kq + 0) * AS2_STRIDE + m] = fmaxf(v.x, 0.f);
            As[(kq + 1) * AS2_STRIDE + m] = fmaxf(v.y, 0.f);
            As[(kq + 2) * AS2_STRIDE + m] = fmaxf(v.z, 0.f);
            As[(kq + 3) * AS2_STRIDE + m] = fmaxf(v.w, 0.f);
        }
        {
            const float4* src = (const float4*)(g_p1t + k0 * CH);
            float4* dst = (float4*)Bs;
#pragma unroll
            for (int i = 0; i < 4; ++i) dst[tid + i * 256] = src[tid + i * 256];
        }
        __syncthreads();
#pragma unroll
        for (int kk = 0; kk < KC; ++kk) {
            const float* ar = &As[kk * AS2_STRIDE + r8];
            ulonglong2 A0 = *(const ulonglong2*)(ar + 0);
            ulonglong2 A1 = *(const ulonglong2*)(ar + 4);
            float4 bv = *(const float4*)&Bs[kk * CH + c4];
            unsigned long long b0 = dup2(bv.x), b1 = dup2(bv.y),
                               b2 = dup2(bv.z), b3 = dup2(bv.w);
            unsigned long long ap[4] = {A0.x, A0.y, A1.x, A1.y};
#pragma unroll
            for (int rp = 0; rp < 4; ++rp) {
                acc[rp][0] = fma2(ap[rp], b0, acc[rp][0]);
                acc[rp][1] = fma2(ap[rp], b1, acc[rp][1]);
                acc[rp][2] = fma2(ap[rp], b2, acc[rp][2]);
                acc[rp][3] = fma2(ap[rp], b3, acc[rp][3]);
            }
        }
    }
    {
        const float4 b1v = *(const float4*)&p1b[c4];
        float bj[4] = {b1v.x, b1v.y, b1v.z, b1v.w};
#pragma unroll
        for (int rp = 0; rp < 4; ++rp) {
            int m = r8 + 2 * rp;
#pragma unroll
            for (int j = 0; j < 4; ++j) {
                float lo, hi;
                unpack2(acc[rp][j], lo, hi);
                lo = fmaxf(lo + bj[j], 0.f);
                hi = fmaxf(hi + bj[j], 0.f);
                *(unsigned long long*)&S1t[(c4 + j) * S1_STRIDE + m] = pack2(lo, hi);
            }
        }
    }
    __syncthreads();

    for (int half = 0; half < 2; ++half) {
#pragma unroll
        for (int i = 0; i < 4; ++i)
#pragma unroll
            for (int j = 0; j < 4; ++j) acc[i][j] = 0ULL;

        for (int k0 = 0; k0 < CH; k0 += KC) {
            __syncthreads();
#pragma unroll
            for (int i = 0; i < 4; ++i) {
                int e  = tid + i * 256;
                int kk = e >> 5;
                int o4 = (e & 31) * 4;
                *(float4*)&Bs[kk * CH + o4] =
                    *(const float4*)(g_p2t + (size_t)(k0 + kk) * 256 + half * 128 + o4);
            }
            __syncthreads();
#pragma unroll
            for (int kk = 0; kk < KC; ++kk) {
                const float* ar = &S1t[(k0 + kk) * S1_STRIDE + r8];
                ulonglong2 A0 = *(const ulonglong2*)(ar + 0);
                ulonglong2 A1 = *(const ulonglong2*)(ar + 4);
                float4 bv = *(const float4*)&Bs[kk * CH + c4];
                unsigned long long b0 = dup2(bv.x), b1 = dup2(bv.y),
                                   b2 = dup2(bv.z), b3 = dup2(bv.w);
                unsigned long long ap[4] = {A0.x, A0.y, A1.x, A1.y};
#pragma unroll
                for (int rp = 0; rp < 4; ++rp) {
                    acc[rp][0] = fma2(ap[rp], b0, acc[rp][0]);
                    acc[rp][1] = fma2(ap[rp], b1, acc[rp][1]);
                    acc[rp][2] = fma2(ap[rp], b2, acc[rp][2]);
                    acc[rp][3] = fma2(ap[rp], b3, acc[rp][3]);
                }
            }
        }
        {
            const float4 b2v = *(const float4*)&p2b[half * 128 + c4];
            float bj[4] = {b2v.x, b2v.y, b2v.z, b2v.w};
#pragma unroll
            for (int rp = 0; rp < 4; ++rp) {
                int m = r8 + 2 * rp;
#pragma unroll
                for (int j = 0; j < 4; ++j) {
                    float lo, hi;
                    unpack2(acc[rp][j], lo, hi);
                    S2[m * S2_STRIDE + c4 + j]       = lo + bj[j];
                    S2[(m + 1) * S2_STRIDE + c4 + j] = hi + bj[j];
                }
            }
        }
        __syncthreads();
        float* outB = out + ((size_t)b * 256 + half * 128) * T_LEN;
#pragma unroll
        for (int i = 0; i < 32; ++i) {
            int e = tid + i * 256;
            int q = e >> 6;
            int t = e & 63;
            outB[(size_t)q * T_LEN + t0 + t] = S2[t * S2_STRIDE + q];
        }
        __syncthreads();
    }
}

// ---------------- launch ----------------
extern "C" void kernel_launch(void* const* d_in, const int* in_sizes, int n_in,
                              void* d_out, int out_size) {
    (void)in_sizes; (void)n_in; (void)out_size;
    const float* x        = (const float*)d_in[0];
    const float* causal_w = (const float*)d_in[1];
    const float* causal_b = (const float*)d_in[2];
    const float* dcnn_w   = (const float*)d_in[3];
    const float* dcnn_b   = (const float*)d_in[4];
    const float* dense_w  = (const float*)d_in[5];
    const float* dense_b  = (const float*)d_in[6];
    const float* skip_w   = (const float*)d_in[7];
    const float* skip_b   = (const float*)d_in[8];
    const float* p1w      = (const float*)d_in[9];
    const float* p1b      = (const float*)d_in[10];
    const float* p2w      = (const float*)d_in[11];
    const float* p2b      = (const float*)d_in[12];
    float* out = (float*)d_out;

    cudaFuncSetAttribute(layer_kernel, cudaFuncAttributeMaxDynamicSharedMemorySize,
                         SMEM_LAYER_BYTES);
    cudaFuncSetAttribute(post_kernel, cudaFuncAttributeMaxDynamicSharedMemorySize,
                         SMEM_POST_BYTES);

    prep_kernel<<<512, 256>>>(dcnn_w, dense_w, skip_w, p1w, p2w);
    causal_kernel<<<dim3(T_LEN / 64, BATCH), 128>>>(x, causal_w, causal_b);
    split0_kernel<<<(SP_ELEMS + 255) / 256, 256>>>();

    for (int cnt = 0; cnt < NLAYER; ++cnt) {
        int dil       = 1 << (cnt % 9);
        int skip_mode = (cnt < N0SKIP) ? 0 : ((cnt == N0SKIP) ? 1 : 2);
        int do_dense  = (cnt != NLAYER - 1);
        int pp        = cnt & 1;
        layer_kernel<<<dim3(T_LEN / TM_L, BATCH), 256, SMEM_LAYER_BYTES>>>(
            cnt, dil, skip_mode, do_dense, pp, dcnn_b, dense_b, skip_b);
    }

    post_kernel<<<dim3(T_LEN / TM_P, BATCH), 256, SMEM_POST_BYTES>>>(p1b, p2b, out);
}

// round 14
// speedup vs baseline: 1.0754x; 1.0754x over previous
#include <cuda_runtime.h>
#include <cstdint>

// ---------------- problem constants ----------------
#define T_LEN   16384
#define CH      128
#define BATCH   8
#define NLAYER  63
#define N0SKIP  27
#define TM_L    128

#define ACT_ELEMS (8u * 16384u * 128u)   // 16,777,216

// layer smem: Yp [8 ks2][128 m][4 tig] uint4 = 4096 u4 (64KB)
#define YP_U4 4096
#define SMEM_LAYER_BYTES (YP_U4 * 16)    // 65536

// split activation buffers: uint4 per (b, t, ks 0..7, tig 0..3)
#define SP_ELEMS (8u * 16384u * 32u)     // 4,194,304 uint4 = 64MB each

// post kernel (FFMA2)
#define KC          32
#define TM_P        64
#define AS2_STRIDE  68
#define S1_STRIDE   68
#define S2_STRIDE   133
#define SMEM_POST_FLOATS (KC*AS2_STRIDE + KC*CH + CH*S1_STRIDE + TM_P*S2_STRIDE)
#define SMEM_POST_BYTES  (SMEM_POST_FLOATS * 4)    // 93952

// ---------------- device scratch ----------------
__device__ float g_bufA[ACT_ELEMS];
__device__ float g_bufB[ACT_ELEMS];
__device__ float g_skip[ACT_ELEMS];
__device__ uint4 g_spA[SP_ELEMS];   // split(relu(x)) fragment-packed, ping
__device__ uint4 g_spB[SP_ELEMS];   // pong
// bf16 hi/lo fragment-packed weights: uint4 = {hi_pair_k, hi_pair_k8, lo_pair_k, lo_pair_k8}
__device__ uint4 g_w3f[NLAYER * 3 * 8 * 128 * 4];   // [cnt][tap][ks16][n][tig]
__device__ uint4 g_wdf[NLAYER * 8 * 128 * 4];       // [cnt][ks16][n][tig]
__device__ uint4 g_wsf[NLAYER * 8 * 128 * 4];       // [cnt][ks16][n][tig]
__device__ float g_p1t[CH * CH];                    // [c][n]
__device__ float g_p2t[CH * 256];                   // [n][q]

// ---------------- helpers ----------------
__device__ __forceinline__ unsigned pack_bf16x2(float lo_val, float hi_val) {
    unsigned r;
    asm("cvt.rn.bf16x2.f32 %0, %1, %2;" : "=r"(r) : "f"(hi_val), "f"(lo_val));
    return r;
}
__device__ __forceinline__ void split_pair(float v0, float v1, unsigned& h, unsigned& l) {
    h = pack_bf16x2(v0, v1);
    float h0 = __uint_as_float(h << 16);
    float h1 = __uint_as_float(h & 0xFFFF0000u);
    l = pack_bf16x2(v0 - h0, v1 - h1);
}
__device__ __forceinline__ void mma16(float* d,
                                      unsigned a0, unsigned a1, unsigned a2, unsigned a3,
                                      unsigned b0, unsigned b1) {
    asm("mma.sync.aligned.m16n8k16.row.col.f32.bf16.bf16.f32 "
        "{%0,%1,%2,%3}, {%4,%5,%6,%7}, {%8,%9}, {%0,%1,%2,%3};"
        : "+f"(d[0]), "+f"(d[1]), "+f"(d[2]), "+f"(d[3])
        : "r"(a0), "r"(a1), "r"(a2), "r"(a3), "r"(b0), "r"(b1));
}
__device__ __forceinline__ unsigned long long fma2(unsigned long long a,
                                                   unsigned long long b,
                                                   unsigned long long c) {
    unsigned long long d;
    asm("fma.rn.f32x2 %0, %1, %2, %3;" : "=l"(d) : "l"(a), "l"(b), "l"(c));
    return d;
}
__device__ __forceinline__ unsigned long long dup2(float x) {
    unsigned long long d;
    asm("mov.b64 %0, {%1, %1};" : "=l"(d) : "f"(x));
    return d;
}
__device__ __forceinline__ unsigned long long pack2(float lo, float hi) {
    unsigned long long d;
    asm("mov.b64 %0, {%1, %2};" : "=l"(d) : "f"(lo), "f"(hi));
    return d;
}
__device__ __forceinline__ void unpack2(unsigned long long v, float& lo, float& hi) {
    asm("mov.b64 {%0, %1}, %2;" : "=f"(lo), "=f"(hi) : "l"(v));
}

// ---------------- weight prep: split + fragment-pack ----------------
__global__ void prep_kernel(const float* __restrict__ dcnn_w,
                            const float* __restrict__ dense_w,
                            const float* __restrict__ skip_w,
                            const float* __restrict__ p1w,
                            const float* __restrict__ p2w) {
    int gs  = gridDim.x * blockDim.x;
    int tid = blockIdx.x * blockDim.x + threadIdx.x;

    const int N3 = NLAYER * 3 * 8 * 128 * 4;
    for (int idx = tid; idx < N3; idx += gs) {
        int tig = idx & 3;
        int n   = (idx >> 2) & 127;
        int ks  = (idx >> 9) & 7;
        int rest = idx >> 12;
        int tap = rest % 3;
        int cnt = rest / 3;
        int k0 = ks * 16 + 2 * tig;
        const float* src = dcnn_w + ((size_t)(cnt * CH + n) * CH) * 3 + tap;
        float w0 = src[(k0 + 0) * 3];
        float w1 = src[(k0 + 1) * 3];
        float w8 = src[(k0 + 8) * 3];
        float w9 = src[(k0 + 9) * 3];
        unsigned hx, lx, hy, ly;
        split_pair(w0, w1, hx, lx);
        split_pair(w8, w9, hy, ly);
        g_w3f[idx] = make_uint4(hx, hy, lx, ly);
    }
    const int N1 = NLAYER * 8 * 128 * 4;
    for (int idx = tid; idx < N1; idx += gs) {
        int tig = idx & 3;
        int n   = (idx >> 2) & 127;
        int ks  = (idx >> 9) & 7;
        int cnt = idx >> 12;
        int k0 = ks * 16 + 2 * tig;
        {
            const float* src = dense_w + (size_t)(cnt * CH + n) * CH;
            unsigned hx, lx, hy, ly;
            split_pair(src[k0], src[k0 + 1], hx, lx);
            split_pair(src[k0 + 8], src[k0 + 9], hy, ly);
            g_wdf[idx] = make_uint4(hx, hy, lx, ly);
        }
        {
            const float* src = skip_w + (size_t)(cnt * CH + n) * CH;
            unsigned hx, lx, hy, ly;
            split_pair(src[k0], src[k0 + 1], hx, lx);
            split_pair(src[k0 + 8], src[k0 + 9], hy, ly);
            g_wsf[idx] = make_uint4(hx, hy, lx, ly);
        }
    }
    for (int idx = tid; idx < CH * CH; idx += gs) {
        int n = idx & 127;
        int c = idx >> 7;
        g_p1t[idx] = p1w[n * CH + c];
    }
    for (int idx = tid; idx < CH * 256; idx += gs) {
        int q = idx & 255;
        int n = idx >> 8;
        g_p2t[idx] = p2w[q * CH + n];
    }
}

// ---------------- causal conv (k=25, pad 12), 1 -> 128 channels ----------------
__global__ void causal_kernel(const float* __restrict__ x,
                              const float* __restrict__ cw,
                              const float* __restrict__ cb) {
    __shared__ float xs[64 + 24];
    int b  = blockIdx.y;
    int t0 = blockIdx.x * 64;
    int c  = threadIdx.x;

    for (int i = threadIdx.x; i < 88; i += 128) {
        int t = t0 - 12 + i;
        xs[i] = ((unsigned)t < T_LEN) ? x[(size_t)b * T_LEN + t] : 0.f;
    }
    __syncthreads();

    float w[25];
#pragma unroll
    for (int k = 0; k < 25; ++k) w[k] = cw[c * 25 + k];
    float bias = cb[c];

    float* out = g_bufA + (size_t)b * T_LEN * CH;
    for (int tt = 0; tt < 64; ++tt) {
        float s = bias;
#pragma unroll
        for (int k = 0; k < 25; ++k) s += w[k] * xs[tt + k];
        out[(size_t)(t0 + tt) * CH + c] = s;
    }
}

// ---------------- initial split of relu(g_bufA) into g_spA ----------------
__global__ void split0_kernel() {
    unsigned idx = blockIdx.x * blockDim.x + threadIdx.x;   // one uint4 each
    if (idx >= SP_ELEMS) return;
    int tig = idx & 3;
    int ks  = (idx >> 2) & 7;
    unsigned bt = idx >> 5;
    const float* row = g_bufA + (size_t)bt * CH;
    int c0 = ks * 16 + 2 * tig;
    unsigned h0, l0, h1, l1;
    split_pair(fmaxf(row[c0], 0.f),     fmaxf(row[c0 + 1], 0.f), h0, l0);
    split_pair(fmaxf(row[c0 + 8], 0.f), fmaxf(row[c0 + 9], 0.f), h1, l1);
    g_spA[idx] = make_uint4(h0, h1, l0, l1);
}

// ---------------- one residual layer (bf16x3, barrier-free stage 1) ----------------
// y = relu(dconv(relu(xin)) + b3) ; skip (+)= y@Ws + bs ; xout = y@Wd + bd + xin
// Stage-1 A operands are LDG'd directly from the fragment-packed split buffer.
__global__ void __launch_bounds__(256, 2)
layer_kernel(int cnt, int dil, int skip_mode, int do_dense, int pp,
             const float* __restrict__ dcnn_b,
             const float* __restrict__ dense_b,
             const float* __restrict__ skip_b) {
    extern __shared__ uint4 Yp[];      // [8 ks][128 m][4 tig]

    const float* xin  = pp ? g_bufB : g_bufA;
    float*       xout = pp ? g_bufA : g_bufB;
    const uint4* spIn = pp ? g_spB : g_spA;
    uint4*       spOut = pp ? g_spA : g_spB;

    int b   = blockIdx.y;
    int t0  = blockIdx.x * TM_L;
    int tid = threadIdx.x;
    int lane = tid & 31, w = tid >> 5;
    int gid = lane >> 2, tig = lane & 3;
    int mw = w & 3, nw = w >> 2;       // 4 m-warps x 2 n-warps
    int m0 = mw * 32, n0 = nw * 64;

    const float* xinB = xin + (size_t)b * T_LEN * CH;
    const uint4* spInB = spIn + (size_t)b * T_LEN * 32;

    float acc[2][8][4];
#pragma unroll
    for (int mt = 0; mt < 2; ++mt)
#pragma unroll
        for (int nt = 0; nt < 8; ++nt)
#pragma unroll
            for (int q = 0; q < 4; ++q) acc[mt][nt][q] = 0.f;

    // ---- stage 1: y = relu(dilated 3-tap conv of relu(xin)), no barriers ----
#pragma unroll 1
    for (int tap = 0; tap < 3; ++tap) {
        int shift = (tap - 1) * dil;
        const uint4* wtap = g_w3f + (size_t)((cnt * 3 + tap) * 8) * 512;
#pragma unroll 1
        for (int ks = 0; ks < 8; ++ks) {
            const uint4* bbase = wtap + (size_t)ks * 512;
            uint4 bf[8];
#pragma unroll
            for (int nt = 0; nt < 8; ++nt)
                bf[nt] = bbase[(n0 + nt * 8 + gid) * 4 + tig];
#pragma unroll
            for (int mt = 0; mt < 2; ++mt) {
                int t_lo = t0 + m0 + mt * 16 + gid + shift;
                int t_hi = t_lo + 8;
                uint4 alo = make_uint4(0u, 0u, 0u, 0u);
                uint4 ahi = make_uint4(0u, 0u, 0u, 0u);
                if ((unsigned)t_lo < T_LEN)
                    alo = spInB[(size_t)t_lo * 32 + ks * 4 + tig];
                if ((unsigned)t_hi < T_LEN)
                    ahi = spInB[(size_t)t_hi * 32 + ks * 4 + tig];
#pragma unroll
                for (int nt = 0; nt < 8; ++nt) {
                    mma16(acc[mt][nt], alo.x, ahi.x, alo.y, ahi.y, bf[nt].x, bf[nt].y);
                    mma16(acc[mt][nt], alo.x, ahi.x, alo.y, ahi.y, bf[nt].z, bf[nt].w);
                    mma16(acc[mt][nt], alo.z, ahi.z, alo.w, ahi.w, bf[nt].x, bf[nt].y);
                }
            }
        }
    }

    // stage-1 epilogue: bias + relu -> Yp (fragment-packed hi/lo)
    {
        const float* db = dcnn_b + cnt * CH;
#pragma unroll
        for (int p = 0; p < 4; ++p) {
            int chE = n0 + (2 * p) * 8 + 2 * tig;
            int chO = chE + 8;
            float2 bE = *(const float2*)(db + chE);
            float2 bO = *(const float2*)(db + chO);
#pragma unroll
            for (int mt = 0; mt < 2; ++mt) {
                int r = m0 + mt * 16 + gid;
                unsigned hE, lE, hO, lO;
                split_pair(fmaxf(acc[mt][2 * p][0] + bE.x, 0.f),
                           fmaxf(acc[mt][2 * p][1] + bE.y, 0.f), hE, lE);
                split_pair(fmaxf(acc[mt][2 * p + 1][0] + bO.x, 0.f),
                           fmaxf(acc[mt][2 * p + 1][1] + bO.y, 0.f), hO, lO);
                Yp[((nw * 4 + p) * 128 + r) * 4 + tig] = make_uint4(hE, hO, lE, lO);
                split_pair(fmaxf(acc[mt][2 * p][2] + bE.x, 0.f),
                           fmaxf(acc[mt][2 * p][3] + bE.y, 0.f), hE, lE);
                split_pair(fmaxf(acc[mt][2 * p + 1][2] + bO.x, 0.f),
                           fmaxf(acc[mt][2 * p + 1][3] + bO.y, 0.f), hO, lO);
                Yp[((nw * 4 + p) * 128 + r + 8) * 4 + tig] = make_uint4(hE, hO, lE, lO);
            }
        }
    }
    __syncthreads();   // the only barrier: Yp complete before stage 2

    // ---- stage 2: skip GEMM (g=0) and dense GEMM (g=1), A = Yp ----
#pragma unroll 1
    for (int g = 0; g < 2; ++g) {
        if (g == 0 && skip_mode == 0) continue;
        if (g == 1 && !do_dense) continue;
        const uint4* wbase = (g == 0 ? g_wsf : g_wdf) + (size_t)(cnt * 8) * 512;
#pragma unroll
        for (int mt = 0; mt < 2; ++mt)
#pragma unroll
            for (int nt = 0; nt < 8; ++nt)
#pragma unroll
                for (int q = 0; q < 4; ++q) acc[mt][nt][q] = 0.f;

#pragma unroll 1
        for (int ky = 0; ky < 8; ++ky) {
            const uint4* bbase = wbase + (size_t)ky * 512;
            uint4 bf[8];
#pragma unroll
            for (int nt = 0; nt < 8; ++nt)
                bf[nt] = bbase[(n0 + nt * 8 + gid) * 4 + tig];
#pragma unroll
            for (int mt = 0; mt < 2; ++mt) {
                int r = m0 + mt * 16 + gid;
                uint4 alo = Yp[(ky * 128 + r) * 4 + tig];
                uint4 ahi = Yp[(ky * 128 + r + 8) * 4 + tig];
#pragma unroll
                for (int nt = 0; nt < 8; ++nt) {
                    mma16(acc[mt][nt], alo.x, ahi.x, alo.y, ahi.y, bf[nt].x, bf[nt].y);
                    mma16(acc[mt][nt], alo.x, ahi.x, alo.y, ahi.y, bf[nt].z, bf[nt].w);
                    mma16(acc[mt][nt], alo.z, ahi.z, alo.w, ahi.w, bf[nt].x, bf[nt].y);
                }
            }
        }

        if (g == 0) {
            const float* sb = skip_b + cnt * CH;
            float* skB = g_skip + (size_t)b * T_LEN * CH;
#pragma unroll
            for (int nt = 0; nt < 8; ++nt) {
                int ch = n0 + nt * 8 + 2 * tig;
                float2 bb = *(const float2*)(sb + ch);
#pragma unroll
                for (int mt = 0; mt < 2; ++mt) {
                    int t_r = t0 + m0 + mt * 16 + gid;
                    float2* p0 = (float2*)(skB + (size_t)t_r * CH + ch);
                    float2* p1 = (float2*)(skB + (size_t)(t_r + 8) * CH + ch);
                    float2 v0 = make_float2(acc[mt][nt][0] + bb.x, acc[mt][nt][1] + bb.y);
                    float2 v1 = make_float2(acc[mt][nt][2] + bb.x, acc[mt][nt][3] + bb.y);
                    if (skip_mode == 2) {
                        float2 o0 = *p0, o1 = *p1;
                        v0.x += o0.x; v0.y += o0.y;
                        v1.x += o1.x; v1.y += o1.y;
                    }
                    *p0 = v0;
                    *p1 = v1;
                }
            }
        } else {
            // dense epilogue: write xout fp32 AND next layer's split fragments
            const float* dbv = dense_b + cnt * CH;
            float* xoB = xout + (size_t)b * T_LEN * CH;
            uint4* spOutB = spOut + (size_t)b * T_LEN * 32;
#pragma unroll
            for (int ntp = 0; ntp < 4; ++ntp) {
                int nt0 = 2 * ntp, nt1 = nt0 + 1;
                int chE = n0 + nt0 * 8 + 2 * tig;   // half0 pair
                int chO = chE + 8;                  // half1 pair
                int ks  = (n0 >> 4) + ntp;          // split-buffer k-chunk
                float2 bbE = *(const float2*)(dbv + chE);
                float2 bbO = *(const float2*)(dbv + chO);
#pragma unroll
                for (int mt = 0; mt < 2; ++mt) {
                    int t_r = t0 + m0 + mt * 16 + gid;
#pragma unroll
                    for (int rr = 0; rr < 2; ++rr) {
                        int t_cur = t_r + rr * 8;
                        int qb = rr * 2;   // acc slots 0,1 or 2,3
                        float2 xiE = *(const float2*)(xinB + (size_t)t_cur * CH + chE);
                        float2 xiO = *(const float2*)(xinB + (size_t)t_cur * CH + chO);
                        float vE0 = acc[mt][nt0][qb]     + bbE.x + xiE.x;
                        float vE1 = acc[mt][nt0][qb + 1] + bbE.y + xiE.y;
                        float vO0 = acc[mt][nt1][qb]     + bbO.x + xiO.x;
                        float vO1 = acc[mt][nt1][qb + 1] + bbO.y + xiO.y;
                        *(float2*)(xoB + (size_t)t_cur * CH + chE) = make_float2(vE0, vE1);
                        *(float2*)(xoB + (size_t)t_cur * CH + chO) = make_float2(vO0, vO1);
                        unsigned hE, lE, hO, lO;
                        split_pair(fmaxf(vE0, 0.f), fmaxf(vE1, 0.f), hE, lE);
                        split_pair(fmaxf(vO0, 0.f), fmaxf(vO1, 0.f), hO, lO);
                        spOutB[(size_t)t_cur * 32 + ks * 4 + tig] =
                            make_uint4(hE, hO, lE, lO);
                    }
                }
            }
        }
    }
}

// ---------------- post head (FFMA2, fp32) ----------------
__global__ void __launch_bounds__(256, 2)
post_kernel(const float* __restrict__ p1b, const float* __restrict__ p2b,
            float* __restrict__ out) {
    extern __shared__ float sm[];
    float* As  = sm;
    float* Bs  = As + KC * AS2_STRIDE;
    float* S1t = Bs + KC * CH;
    float* S2  = S1t + CH * S1_STRIDE;

    int b    = blockIdx.y;
    int t0   = blockIdx.x * TM_P;
    int tid  = threadIdx.x;
    int lane = tid & 31, warp = tid >> 5;
    int c4   = lane * 4;
    int r8   = warp * 8;

    const float* skB = g_skip + (size_t)b * T_LEN * CH;

    unsigned long long acc[4][4];
#pragma unroll
    for (int i = 0; i < 4; ++i)
#pragma unroll
        for (int j = 0; j < 4; ++j) acc[i][j] = 0ULL;

    for (int k0 = 0; k0 < CH; k0 += KC) {
        __syncthreads();
#pragma unroll
        for (int i = 0; i < 2; ++i) {
            int e4 = tid + i * 256;
            int m  = e4 >> 3;
            int kq = (e4 & 7) * 4;
            float4 v = *(const float4*)(skB + (size_t)(t0 + m) * CH + k0 + kq);
            As[(kq + 0) * AS2_STRIDE + m] = fmaxf(v.x, 0.f);
            As[(kq + 1) * AS2_STRIDE + m] = fmaxf(v.y, 0.f);
            As[(kq + 2) * AS2_STRIDE + m] = fmaxf(v.z, 0.f);
            As[(kq + 3) * AS2_STRIDE + m] = fmaxf(v.w, 0.f);
        }
        {
            const float4* src = (const float4*)(g_p1t + k0 * CH);
            float4* dst = (float4*)Bs;
#pragma unroll
            for (int i = 0; i < 4; ++i) dst[tid + i * 256] = src[tid + i * 256];
        }
        __syncthreads();
#pragma unroll
        for (int kk = 0; kk < KC; ++kk) {
            const float* ar = &As[kk * AS2_STRIDE + r8];
            ulonglong2 A0 = *(const ulonglong2*)(ar + 0);
            ulonglong2 A1 = *(const ulonglong2*)(ar + 4);
            float4 bv = *(const float4*)&Bs[kk * CH + c4];
            unsigned long long b0 = dup2(bv.x), b1 = dup2(bv.y),
                               b2 = dup2(bv.z), b3 = dup2(bv.w);
            unsigned long long ap[4] = {A0.x, A0.y, A1.x, A1.y};
#pragma unroll
            for (int rp = 0; rp < 4; ++rp) {
                acc[rp][0] = fma2(ap[rp], b0, acc[rp][0]);
                acc[rp][1] = fma2(ap[rp], b1, acc[rp][1]);
                acc[rp][2] = fma2(ap[rp], b2, acc[rp][2]);
                acc[rp][3] = fma2(ap[rp], b3, acc[rp][3]);
            }
        }
    }
    {
        const float4 b1v = *(const float4*)&p1b[c4];
        float bj[4] = {b1v.x, b1v.y, b1v.z, b1v.w};
#pragma unroll
        for (int rp = 0; rp < 4; ++rp) {
            int m = r8 + 2 * rp;
#pragma unroll
            for (int j = 0; j < 4; ++j) {
                float lo, hi;
                unpack2(acc[rp][j], lo, hi);
                lo = fmaxf(lo + bj[j], 0.f);
                hi = fmaxf(hi + bj[j], 0.f);
                *(unsigned long long*)&S1t[(c4 + j) * S1_STRIDE + m] = pack2(lo, hi);
            }
        }
    }
    __syncthreads();

    for (int half = 0; half < 2; ++half) {
#pragma unroll
        for (int i = 0; i < 4; ++i)
#pragma unroll
            for (int j = 0; j < 4; ++j) acc[i][j] = 0ULL;

        for (int k0 = 0; k0 < CH; k0 += KC) {
            __syncthreads();
#pragma unroll
            for (int i = 0; i < 4; ++i) {
                int e  = tid + i * 256;
                int kk = e >> 5;
                int o4 = (e & 31) * 4;
                *(float4*)&Bs[kk * CH + o4] =
                    *(const float4*)(g_p2t + (size_t)(k0 + kk) * 256 + half * 128 + o4);
            }
            __syncthreads();
#pragma unroll
            for (int kk = 0; kk < KC; ++kk) {
                const float* ar = &S1t[(k0 + kk) * S1_STRIDE + r8];
                ulonglong2 A0 = *(const ulonglong2*)(ar + 0);
                ulonglong2 A1 = *(const ulonglong2*)(ar + 4);
                float4 bv = *(const float4*)&Bs[kk * CH + c4];
                unsigned long long b0 = dup2(bv.x), b1 = dup2(bv.y),
                                   b2 = dup2(bv.z), b3 = dup2(bv.w);
                unsigned long long ap[4] = {A0.x, A0.y, A1.x, A1.y};
#pragma unroll
                for (int rp = 0; rp < 4; ++rp) {
                    acc[rp][0] = fma2(ap[rp], b0, acc[rp][0]);
                    acc[rp][1] = fma2(ap[rp], b1, acc[rp][1]);
                    acc[rp][2] = fma2(ap[rp], b2, acc[rp][2]);
                    acc[rp][3] = fma2(ap[rp], b3, acc[rp][3]);
                }
            }
        }
        {
            const float4 b2v = *(const float4*)&p2b[half * 128 + c4];
            float bj[4] = {b2v.x, b2v.y, b2v.z, b2v.w};
#pragma unroll
            for (int rp = 0; rp < 4; ++rp) {
                int m = r8 + 2 * rp;
#pragma unroll
                for (int j = 0; j < 4; ++j) {
                    float lo, hi;
                    unpack2(acc[rp][j], lo, hi);
                    S2[m * S2_STRIDE + c4 + j]       = lo + bj[j];
                    S2[(m + 1) * S2_STRIDE + c4 + j] = hi + bj[j];
                }
            }
        }
        __syncthreads();
        float* outB = out + ((size_t)b * 256 + half * 128) * T_LEN;
#pragma unroll
        for (int i = 0; i < 32; ++i) {
            int e = tid + i * 256;
            int q = e >> 6;
            int t = e & 63;
            outB[(size_t)q * T_LEN + t0 + t] = S2[t * S2_STRIDE + q];
        }
        __syncthreads();
    }
}

// ---------------- launch ----------------
extern "C" void kernel_launch(void* const* d_in, const int* in_sizes, int n_in,
                              void* d_out, int out_size) {
    (void)in_sizes; (void)n_in; (void)out_size;
    const float* x        = (const float*)d_in[0];
    const float* causal_w = (const float*)d_in[1];
    const float* causal_b = (const float*)d_in[2];
    const float* dcnn_w   = (const float*)d_in[3];
    const float* dcnn_b   = (const float*)d_in[4];
    const float* dense_w  = (const float*)d_in[5];
    const float* dense_b  = (const float*)d_in[6];
    const float* skip_w   = (const float*)d_in[7];
    const float* skip_b   = (const float*)d_in[8];
    const float* p1w      = (const float*)d_in[9];
    const float* p1b      = (const float*)d_in[10];
    const float* p2w      = (const float*)d_in[11];
    const float* p2b      = (const float*)d_in[12];
    float* out = (float*)d_out;

    cudaFuncSetAttribute(layer_kernel, cudaFuncAttributeMaxDynamicSharedMemorySize,
                         SMEM_LAYER_BYTES);
    cudaFuncSetAttribute(post_kernel, cudaFuncAttributeMaxDynamicSharedMemorySize,
                         SMEM_POST_BYTES);

    prep_kernel<<<512, 256>>>(dcnn_w, dense_w, skip_w, p1w, p2w);
    causal_kernel<<<dim3(T_LEN / 64, BATCH), 128>>>(x, causal_w, causal_b);
    split0_kernel<<<(SP_ELEMS + 255) / 256, 256>>>();

    for (int cnt = 0; cnt < NLAYER; ++cnt) {
        int dil       = 1 << (cnt % 9);
        int skip_mode = (cnt < N0SKIP) ? 0 : ((cnt == N0SKIP) ? 1 : 2);
        int do_dense  = (cnt != NLAYER - 1);
        int pp        = cnt & 1;
        layer_kernel<<<dim3(T_LEN / TM_L, BATCH), 256, SMEM_LAYER_BYTES>>>(
            cnt, dil, skip_mode, do_dense, pp, dcnn_b, dense_b, skip_b);
    }

    post_kernel<<<dim3(T_LEN / TM_P, BATCH), 256, SMEM_POST_BYTES>>>(p1b, p2b, out);
}